// round 12
// baseline (speedup 1.0000x reference)
#include <cuda_runtime.h>
#include <cuda_fp16.h>

#define N_NODES 50000
#define HF 128          // H*F
#define H_HEADS 4
#define NODES_PER_BLK 32
#define DEG_CAP 128     // bucket capacity; deg ~ Poisson(16), P(>128) < 1e-60
#define KBATCH 8        // W prefetch depth

// ---------------- packed f32x2 helpers (sm_103a) ----------------
#define PACK_F32X2(out, lo, hi) \
    asm("mov.b64 %0, {%1, %2};" : "=l"(out) : "f"(lo), "f"(hi))
#define UNPACK_F32X2(lo, hi, in) \
    asm("mov.b64 {%0, %1}, %2;" : "=f"(lo), "=f"(hi) : "l"(in))
#define FMA_F32X2(d, a, b, c) \
    asm("fma.rn.f32x2 %0, %1, %2, %3;" : "=l"(d) : "l"(a), "l"(b), "l"(c))

// ---------------- scratch (static device globals; no allocation) ----------------
__device__ float g_z[N_NODES * HF];
__device__ float g_acc1[N_NODES * HF];   // layer-1 base -> elu(h1)
__device__ float g_acc2[N_NODES * HF];   // layer-2 base (residual + bias)
__device__ float g_el[N_NODES * H_HEADS];
__device__ float g_er[N_NODES * H_HEADS];
__device__ int   g_cnt[N_NODES];
__device__ int   g_bucket[N_NODES * DEG_CAP];   // 25.6 MB

__device__ __forceinline__ float leaky(float v) { return v > 0.f ? v : 0.2f * v; }
__device__ __forceinline__ float elu(float v)   { return v > 0.f ? v : (__expf(v) - 1.f); }

// ---------------- bucket fill: the entire adjacency build in one kernel ----------------
__global__ void fill_bucket_kernel(const int* __restrict__ src, const int* __restrict__ dst,
                                   int E, int* __restrict__ cnt, int* __restrict__ bucket) {
    int i = blockIdx.x * blockDim.x + threadIdx.x;
    int e0 = i * 4;
    if (e0 + 4 <= E) {
        int4 d4 = *reinterpret_cast<const int4*>(dst + e0);
        int4 s4 = *reinterpret_cast<const int4*>(src + e0);
        int p0 = atomicAdd(&cnt[d4.x], 1);
        int p1 = atomicAdd(&cnt[d4.y], 1);
        int p2 = atomicAdd(&cnt[d4.z], 1);
        int p3 = atomicAdd(&cnt[d4.w], 1);
        bucket[d4.x * DEG_CAP + p0] = s4.x;
        bucket[d4.y * DEG_CAP + p1] = s4.y;
        bucket[d4.z * DEG_CAP + p2] = s4.z;
        bucket[d4.w * DEG_CAP + p3] = s4.w;
    } else {
        for (int e = e0; e < E; e++) {
            int dn = dst[e];
            int pos = atomicAdd(&cnt[dn], 1);
            bucket[dn * DEG_CAP + pos] = src[e];
        }
    }
}

// ---------------- K1: z = x @ W ; LDS.128 x-tile bound directly to u64 pairs ------------
// xs[k][q].x = nodes {4q,4q+1}, .y = nodes {4q+2,4q+3} at feature k.
// One LDS.128 feeds two FFMA2 with no conversion MOVs (u64 register-pair binding).
__global__ __launch_bounds__(128)
void gemm_attn_kernel(const float* __restrict__ x,
                      const float* __restrict__ W,
                      const float* __restrict__ al,
                      const float* __restrict__ ar,
                      const float* __restrict__ bias,
                      float* __restrict__ z,
                      float* __restrict__ base,
                      float* __restrict__ el,
                      float* __restrict__ er)
{
    __shared__ ulonglong2 xs[HF][9];  // 8 used + 1 pad -> 144B row stride; 18.4 KB
    const int j  = threadIdx.x;       // 0..127 output column
    const int n0 = blockIdx.x * NODES_PER_BLK;
    const float bj = bias[j];

    #pragma unroll
    for (int nn = 0; nn < NODES_PER_BLK; nn++) {
        int n = n0 + nn;
        float xv = 0.f;
        if (n < N_NODES) {
            xv = x[n * HF + j];
            base[n * HF + j] = xv + bj;       // residual + bias, written up front
        }
        reinterpret_cast<float*>(&xs[j][0])[nn] = xv;
    }
    __syncthreads();

    unsigned long long acc[NODES_PER_BLK / 2];
    #pragma unroll
    for (int p = 0; p < NODES_PER_BLK / 2; p++) acc[p] = 0ull;  // {0.f, 0.f}

    #pragma unroll 1
    for (int kk = 0; kk < HF; kk += KBATCH) {
        // batch-prefetch KBATCH W values (8 independent LDGs in flight)
        unsigned long long wp[KBATCH];
        #pragma unroll
        for (int t = 0; t < KBATCH; t++) {
            float w = W[(kk + t) * HF + j];
            PACK_F32X2(wp[t], w, w);
        }
        #pragma unroll
        for (int t = 0; t < KBATCH; t++) {
            #pragma unroll
            for (int q = 0; q < 8; q++) {   // 8 LDS.128 per k -> 16 FFMA2
                ulonglong2 v = xs[kk + t][q];
                FMA_F32X2(acc[2 * q + 0], v.x, wp[t], acc[2 * q + 0]);
                FMA_F32X2(acc[2 * q + 1], v.y, wp[t], acc[2 * q + 1]);
            }
        }
    }

    const float alj = al[j], arj = ar[j];
    const int h = j >> 5, f = j & 31;

    #pragma unroll
    for (int p = 0; p < NODES_PER_BLK / 2; p++) {
        float slo, shi;
        UNPACK_F32X2(slo, shi, acc[p]);
        #pragma unroll
        for (int q = 0; q < 2; q++) {
            int nn = 2 * p + q;
            int n = n0 + nn;
            if (n >= N_NODES) break;      // uniform across warp
            float s = q ? shi : slo;
            z[n * HF + j] = s;
            float pl = s * alj;
            float pr = s * arj;
            #pragma unroll
            for (int off = 16; off; off >>= 1) {
                pl += __shfl_down_sync(0xffffffffu, pl, off);
                pr += __shfl_down_sync(0xffffffffu, pr, off);
            }
            if (f == 0) {
                el[n * H_HEADS + h] = pl;
                er[n * H_HEADS + h] = pr;
            }
        }
    }
}

// ---------------- single-pass softmax-free aggregate, one warp per node -----------------
// h_n = base_n + (sum_i e_i * z_{src_i}) / (sum_i e_i).  R6-proven loop shape, fp32 z.
// MODE 0: layer-1 epilogue -> elu(acc) stored to hio (becomes layer-2 input)
// MODE 1: layer-2 epilogue -> head-mean + projection, writes out[n] only
template <int MODE>
__global__ __launch_bounds__(256)
void gat_aggregate_kernel(const int* __restrict__ cnt,
                          const int* __restrict__ bucket,
                          const float* __restrict__ el, const float* __restrict__ er,
                          const float* __restrict__ z,
                          float* __restrict__ hio,          // base in, result out (MODE 0)
                          const float* __restrict__ Wp, const float* __restrict__ bp,
                          float* __restrict__ out)
{
    const int wid  = threadIdx.x >> 5;
    const int lane = threadIdx.x & 31;
    const int n    = blockIdx.x * 8 + wid;
    if (n >= N_NODES) return;

    const int beg = n * DEG_CAP;
    const int d   = cnt[n];
    const int h   = lane >> 3;

    const float erh = __ldg(&er[n * H_HEADS + h]);

    float  s   = 0.f;
    float4 acc = make_float4(0.f, 0.f, 0.f, 0.f);

    for (int i = 0; i < d; ++i) {
        int   sn = __ldg(&bucket[beg + i]);                        // warp-uniform
        float ev = __expf(leaky(__ldg(&el[sn * H_HEADS + h]) + erh));
        float4 zv = *reinterpret_cast<const float4*>(z + sn * HF + lane * 4);
        s     += ev;
        acc.x += ev * zv.x;
        acc.y += ev * zv.y;
        acc.z += ev * zv.z;
        acc.w += ev * zv.w;
    }

    const float sinv = 1.f / fmaxf(s, 1e-9f);
    float4 base = *reinterpret_cast<const float4*>(hio + n * HF + lane * 4);
    acc.x = base.x + acc.x * sinv;
    acc.y = base.y + acc.y * sinv;
    acc.z = base.z + acc.z * sinv;
    acc.w = base.w + acc.w * sinv;

    if (MODE == 0) {
        // ELU here so layer-2 GEMM (and its residual) read the activated value directly
        acc.x = elu(acc.x); acc.y = elu(acc.y); acc.z = elu(acc.z); acc.w = elu(acc.w);
        *reinterpret_cast<float4*>(hio + n * HF + lane * 4) = acc;
    } else {
        // head-mean + projection: out[n] = 0.25 * sum_{h,f} acc[h][f] * Wp[f] + bp
        const int f0 = (lane & 7) * 4;
        float v = acc.x * Wp[f0] + acc.y * Wp[f0 + 1] + acc.z * Wp[f0 + 2] + acc.w * Wp[f0 + 3];
        #pragma unroll
        for (int off = 16; off; off >>= 1) v += __shfl_down_sync(0xffffffffu, v, off);
        if (lane == 0) out[n] = 0.25f * v + bp[0];
    }
}

// ---------------- launch ----------------
extern "C" void kernel_launch(void* const* d_in, const int* in_sizes, int n_in,
                              void* d_out, int out_size)
{
    const float* feats = (const float*)d_in[0];
    const int*   src   = (const int*)  d_in[1];
    const int*   dst   = (const int*)  d_in[2];
    const float* W1    = (const float*)d_in[3];
    const float* al1   = (const float*)d_in[4];
    const float* ar1   = (const float*)d_in[5];
    const float* b1    = (const float*)d_in[6];
    const float* W2    = (const float*)d_in[7];
    const float* al2   = (const float*)d_in[8];
    const float* ar2   = (const float*)d_in[9];
    const float* b2    = (const float*)d_in[10];
    const float* Wp    = (const float*)d_in[11];
    const float* bp    = (const float*)d_in[12];
    float* out = (float*)d_out;

    const int E = in_sizes[1];

    float *z, *acc1, *acc2, *el, *er;
    int *cnt, *bucket;
    cudaGetSymbolAddress((void**)&z,      g_z);
    cudaGetSymbolAddress((void**)&acc1,   g_acc1);
    cudaGetSymbolAddress((void**)&acc2,   g_acc2);
    cudaGetSymbolAddress((void**)&el,     g_el);
    cudaGetSymbolAddress((void**)&er,     g_er);
    cudaGetSymbolAddress((void**)&cnt,    g_cnt);
    cudaGetSymbolAddress((void**)&bucket, g_bucket);

    const int fill_grid = ((E + 3) / 4 + 255) / 256;
    const int gemm_grid = (N_NODES + NODES_PER_BLK - 1) / NODES_PER_BLK;
    const int agg_grid  = (N_NODES + 7) / 8;

    // ---- adjacency build: memset + ONE kernel ----
    cudaMemsetAsync(cnt, 0, N_NODES * sizeof(int));
    fill_bucket_kernel<<<fill_grid, 256>>>(src, dst, E, cnt, bucket);

    // ---- layer 1 ----
    gemm_attn_kernel<<<gemm_grid, 128>>>(feats, W1, al1, ar1, b1, z, acc1, el, er);
    gat_aggregate_kernel<0><<<agg_grid, 256>>>(cnt, bucket, el, er, z, acc1, Wp, bp, out);

    // ---- layer 2 (input acc1 already ELU'd) + fused head ----
    gemm_attn_kernel<<<gemm_grid, 128>>>(acc1, W2, al2, ar2, b2, z, acc2, el, er);
    gat_aggregate_kernel<1><<<agg_grid, 256>>>(cnt, bucket, el, er, z, acc2, Wp, bp, out);
}

// round 13
// speedup vs baseline: 1.0879x; 1.0879x over previous
#include <cuda_runtime.h>
#include <cuda_fp16.h>

#define N_NODES 50000
#define HF 128          // H*F
#define H_HEADS 4
#define DEG_CAP 128     // bucket capacity; deg ~ Poisson(16), P(>128) < 1e-60
#define GBLK 128        // nodes per GEMM block
#define KCH 32          // K chunk

// ---------------- scratch (static device globals; no allocation) ----------------
__device__ float g_z[N_NODES * HF];
__device__ float g_acc1[N_NODES * HF];   // layer-1 base -> elu(h1)
__device__ float g_acc2[N_NODES * HF];   // layer-2 base (residual + bias)
__device__ float g_el[N_NODES * H_HEADS];
__device__ float g_er[N_NODES * H_HEADS];
__device__ int   g_cnt[N_NODES];
__device__ int   g_bucket[N_NODES * DEG_CAP];   // 25.6 MB

__device__ __forceinline__ float leaky(float v) { return v > 0.f ? v : 0.2f * v; }
__device__ __forceinline__ float elu(float v)   { return v > 0.f ? v : (__expf(v) - 1.f); }

// ---------------- bucket fill: the entire adjacency build in one kernel ----------------
__global__ void fill_bucket_kernel(const int* __restrict__ src, const int* __restrict__ dst,
                                   int E, int* __restrict__ cnt, int* __restrict__ bucket) {
    int i = blockIdx.x * blockDim.x + threadIdx.x;
    int e0 = i * 4;
    if (e0 + 4 <= E) {
        int4 d4 = *reinterpret_cast<const int4*>(dst + e0);
        int4 s4 = *reinterpret_cast<const int4*>(src + e0);
        int p0 = atomicAdd(&cnt[d4.x], 1);
        int p1 = atomicAdd(&cnt[d4.y], 1);
        int p2 = atomicAdd(&cnt[d4.z], 1);
        int p3 = atomicAdd(&cnt[d4.w], 1);
        bucket[d4.x * DEG_CAP + p0] = s4.x;
        bucket[d4.y * DEG_CAP + p1] = s4.y;
        bucket[d4.z * DEG_CAP + p2] = s4.z;
        bucket[d4.w * DEG_CAP + p3] = s4.w;
    } else {
        for (int e = e0; e < E; e++) {
            int dn = dst[e];
            int pos = atomicAdd(&cnt[dn], 1);
            bucket[dn * DEG_CAP + pos] = src[e];
        }
    }
}

// ---------------- K1: register-tiled SGEMM (128x128 tile, 8x8 per thread) --------------
// z[n][j] = sum_k x[n][k] W[k][j]; also el/er row reductions and base = x + bias.
// 256 threads: ng = tid>>4 (node octet), cg = tid&15 (col octet). Lane-varying LDS.128.
__global__ __launch_bounds__(256)
void gemm_attn_kernel(const float* __restrict__ x,
                      const float* __restrict__ W,
                      const float* __restrict__ al,
                      const float* __restrict__ ar,
                      const float* __restrict__ bias,
                      float* __restrict__ z,
                      float* __restrict__ base,
                      float* __restrict__ el,
                      float* __restrict__ er)
{
    __shared__ float xs[KCH][GBLK];   // x chunk, transposed: xs[k][node]  (16 KB)
    __shared__ float ws[KCH][HF];     // W chunk: ws[k][col]               (16 KB)

    const int tid = threadIdx.x;
    const int n0  = blockIdx.x * GBLK;
    const int cg  = tid & 15;         // col octet: cols cg*8..cg*8+7
    const int ng  = tid >> 4;         // node octet: nodes n0+ng*8..+7

    float acc[8][8];
    #pragma unroll
    for (int r = 0; r < 8; r++)
        #pragma unroll
        for (int c = 0; c < 8; c++) acc[r][c] = 0.f;

    const int lrow = tid & 127;       // node row for x loads
    const int c4b  = tid >> 7;        // 0..1

    for (int kc = 0; kc < HF; kc += KCH) {
        // ---- load x chunk (transposed) + write base = x + bias ----
        {
            const int n = n0 + lrow;
            const bool valid = (n < N_NODES);
            #pragma unroll
            for (int it = 0; it < 4; it++) {
                int c4 = c4b + it * 2;            // 0..7 (float4 within chunk)
                int k  = kc + c4 * 4;
                float4 v = make_float4(0.f, 0.f, 0.f, 0.f);
                if (valid) v = *reinterpret_cast<const float4*>(&x[n * HF + k]);
                xs[c4 * 4 + 0][lrow] = v.x;
                xs[c4 * 4 + 1][lrow] = v.y;
                xs[c4 * 4 + 2][lrow] = v.z;
                xs[c4 * 4 + 3][lrow] = v.w;
                if (valid) {
                    float4 b4 = *reinterpret_cast<const float4*>(&bias[k]);
                    float4 o = make_float4(v.x + b4.x, v.y + b4.y, v.z + b4.z, v.w + b4.w);
                    *reinterpret_cast<float4*>(&base[n * HF + k]) = o;
                }
            }
        }
        // ---- load W chunk (already k-major) ----
        {
            #pragma unroll
            for (int it = 0; it < 4; it++) {
                int idx = tid + it * 256;          // float4 index, 0..1023
                int kl  = idx >> 5;                // 32 float4 per k-row
                int c4  = idx & 31;
                float4 v = *reinterpret_cast<const float4*>(&W[(kc + kl) * HF + c4 * 4]);
                *reinterpret_cast<float4*>(&ws[kl][c4 * 4]) = v;
            }
        }
        __syncthreads();

        // ---- outer-product FMA over the chunk ----
        #pragma unroll
        for (int k = 0; k < KCH; k++) {
            float xr[8], wr[8];
            *reinterpret_cast<float4*>(&xr[0]) = *reinterpret_cast<const float4*>(&xs[k][ng * 8]);
            *reinterpret_cast<float4*>(&xr[4]) = *reinterpret_cast<const float4*>(&xs[k][ng * 8 + 4]);
            *reinterpret_cast<float4*>(&wr[0]) = *reinterpret_cast<const float4*>(&ws[k][cg * 8]);
            *reinterpret_cast<float4*>(&wr[4]) = *reinterpret_cast<const float4*>(&ws[k][cg * 8 + 4]);
            #pragma unroll
            for (int r = 0; r < 8; r++)
                #pragma unroll
                for (int c = 0; c < 8; c++)
                    acc[r][c] += xr[r] * wr[c];
        }
        __syncthreads();
    }

    // ---- epilogue: z store, el/er reductions (4-lane groups share a head) ----
    const int h  = cg >> 2;
    const int c0 = cg * 8;
    float alv[8], arv[8];
    #pragma unroll
    for (int c = 0; c < 8; c++) { alv[c] = al[c0 + c]; arv[c] = ar[c0 + c]; }

    #pragma unroll
    for (int r = 0; r < 8; r++) {
        int n = n0 + ng * 8 + r;
        bool valid = (n < N_NODES);
        if (valid) {
            *reinterpret_cast<float4*>(&z[n * HF + c0]) =
                make_float4(acc[r][0], acc[r][1], acc[r][2], acc[r][3]);
            *reinterpret_cast<float4*>(&z[n * HF + c0 + 4]) =
                make_float4(acc[r][4], acc[r][5], acc[r][6], acc[r][7]);
        }
        float pl = 0.f, pr = 0.f;
        #pragma unroll
        for (int c = 0; c < 8; c++) { pl += acc[r][c] * alv[c]; pr += acc[r][c] * arv[c]; }
        pl += __shfl_down_sync(0xffffffffu, pl, 2);
        pl += __shfl_down_sync(0xffffffffu, pl, 1);
        pr += __shfl_down_sync(0xffffffffu, pr, 2);
        pr += __shfl_down_sync(0xffffffffu, pr, 1);
        if (valid && (cg & 3) == 0) {
            el[n * H_HEADS + h] = pl;
            er[n * H_HEADS + h] = pr;
        }
    }
}

// ---------------- single-pass softmax-free aggregate, one warp per node -----------------
// h_n = base_n + (sum_i e_i * z_{src_i}) / (sum_i e_i).  R6-proven loop shape, fp32 z.
// MODE 0: layer-1 epilogue -> elu(acc) stored to hio (becomes layer-2 input)
// MODE 1: layer-2 epilogue -> head-mean + projection, writes out[n] only
template <int MODE>
__global__ __launch_bounds__(256)
void gat_aggregate_kernel(const int* __restrict__ cnt,
                          const int* __restrict__ bucket,
                          const float* __restrict__ el, const float* __restrict__ er,
                          const float* __restrict__ z,
                          float* __restrict__ hio,          // base in, result out (MODE 0)
                          const float* __restrict__ Wp, const float* __restrict__ bp,
                          float* __restrict__ out)
{
    const int wid  = threadIdx.x >> 5;
    const int lane = threadIdx.x & 31;
    const int n    = blockIdx.x * 8 + wid;
    if (n >= N_NODES) return;

    const int beg = n * DEG_CAP;
    const int d   = cnt[n];
    const int h   = lane >> 3;

    const float erh = __ldg(&er[n * H_HEADS + h]);

    float  s   = 0.f;
    float4 acc = make_float4(0.f, 0.f, 0.f, 0.f);

    for (int i = 0; i < d; ++i) {
        int   sn = __ldg(&bucket[beg + i]);                        // warp-uniform
        float ev = __expf(leaky(__ldg(&el[sn * H_HEADS + h]) + erh));
        float4 zv = *reinterpret_cast<const float4*>(z + sn * HF + lane * 4);
        s     += ev;
        acc.x += ev * zv.x;
        acc.y += ev * zv.y;
        acc.z += ev * zv.z;
        acc.w += ev * zv.w;
    }

    const float sinv = 1.f / fmaxf(s, 1e-9f);
    float4 base = *reinterpret_cast<const float4*>(hio + n * HF + lane * 4);
    acc.x = base.x + acc.x * sinv;
    acc.y = base.y + acc.y * sinv;
    acc.z = base.z + acc.z * sinv;
    acc.w = base.w + acc.w * sinv;

    if (MODE == 0) {
        // ELU here so layer-2 GEMM (and its residual) read the activated value directly
        acc.x = elu(acc.x); acc.y = elu(acc.y); acc.z = elu(acc.z); acc.w = elu(acc.w);
        *reinterpret_cast<float4*>(hio + n * HF + lane * 4) = acc;
    } else {
        // head-mean + projection: out[n] = 0.25 * sum_{h,f} acc[h][f] * Wp[f] + bp
        const int f0 = (lane & 7) * 4;
        float v = acc.x * Wp[f0] + acc.y * Wp[f0 + 1] + acc.z * Wp[f0 + 2] + acc.w * Wp[f0 + 3];
        #pragma unroll
        for (int off = 16; off; off >>= 1) v += __shfl_down_sync(0xffffffffu, v, off);
        if (lane == 0) out[n] = 0.25f * v + bp[0];
    }
}

// ---------------- launch ----------------
extern "C" void kernel_launch(void* const* d_in, const int* in_sizes, int n_in,
                              void* d_out, int out_size)
{
    const float* feats = (const float*)d_in[0];
    const int*   src   = (const int*)  d_in[1];
    const int*   dst   = (const int*)  d_in[2];
    const float* W1    = (const float*)d_in[3];
    const float* al1   = (const float*)d_in[4];
    const float* ar1   = (const float*)d_in[5];
    const float* b1    = (const float*)d_in[6];
    const float* W2    = (const float*)d_in[7];
    const float* al2   = (const float*)d_in[8];
    const float* ar2   = (const float*)d_in[9];
    const float* b2    = (const float*)d_in[10];
    const float* Wp    = (const float*)d_in[11];
    const float* bp    = (const float*)d_in[12];
    float* out = (float*)d_out;

    const int E = in_sizes[1];

    float *z, *acc1, *acc2, *el, *er;
    int *cnt, *bucket;
    cudaGetSymbolAddress((void**)&z,      g_z);
    cudaGetSymbolAddress((void**)&acc1,   g_acc1);
    cudaGetSymbolAddress((void**)&acc2,   g_acc2);
    cudaGetSymbolAddress((void**)&el,     g_el);
    cudaGetSymbolAddress((void**)&er,     g_er);
    cudaGetSymbolAddress((void**)&cnt,    g_cnt);
    cudaGetSymbolAddress((void**)&bucket, g_bucket);

    const int fill_grid = ((E + 3) / 4 + 255) / 256;
    const int gemm_grid = (N_NODES + GBLK - 1) / GBLK;
    const int agg_grid  = (N_NODES + 7) / 8;

    // ---- adjacency build: memset + ONE kernel ----
    cudaMemsetAsync(cnt, 0, N_NODES * sizeof(int));
    fill_bucket_kernel<<<fill_grid, 256>>>(src, dst, E, cnt, bucket);

    // ---- layer 1 ----
    gemm_attn_kernel<<<gemm_grid, 256>>>(feats, W1, al1, ar1, b1, z, acc1, el, er);
    gat_aggregate_kernel<0><<<agg_grid, 256>>>(cnt, bucket, el, er, z, acc1, Wp, bp, out);

    // ---- layer 2 (input acc1 already ELU'd) + fused head ----
    gemm_attn_kernel<<<gemm_grid, 256>>>(acc1, W2, al2, ar2, b2, z, acc2, el, er);
    gat_aggregate_kernel<1><<<agg_grid, 256>>>(cnt, bucket, el, er, z, acc2, Wp, bp, out);
}